// round 10
// baseline (speedup 1.0000x reference)
#include <cuda_runtime.h>
#include <cuda_bf16.h>
#include <math.h>
#include <stdint.h>

// Problem dims
#define Bb 4
#define Tt 2048
#define Cc 2048
#define NH 16      // q heads
#define KH 4       // kv heads
#define Hd 128
#define BT (Bb*Tt)          // 8192
#define QW (NH*Hd)          // 2048
#define KW (KH*Hd)          // 512

// Scratch (static device arrays; allocation-free per harness rules)
__device__ float g_q[(size_t)BT*QW];
__device__ float g_k[(size_t)BT*KW];
__device__ float g_v[(size_t)BT*KW];
__device__ float g_enc[(size_t)BT*QW];

// ---------------- TF32 helpers ----------------
__device__ __forceinline__ uint32_t f2tf32(float f) {
    uint32_t r;
    asm("cvt.rna.tf32.f32 %0, %1;" : "=r"(r) : "f"(f));
    return r;
}

__device__ __forceinline__ void mma_tf32(float* c, const uint32_t* a, const uint32_t* b) {
    asm volatile(
        "mma.sync.aligned.m16n8k8.row.col.f32.tf32.tf32.f32 "
        "{%0,%1,%2,%3}, {%4,%5,%6,%7}, {%8,%9}, {%0,%1,%2,%3};\n"
        : "+f"(c[0]), "+f"(c[1]), "+f"(c[2]), "+f"(c[3])
        : "r"(a[0]), "r"(a[1]), "r"(a[2]), "r"(a[3]), "r"(b[0]), "r"(b[1]));
}

// ---------------- TF32 tensor-core GEMM core (projections / out) ----------------
#define BM 128
#define BN 128
#define BK 32
#define SA 36
#define SB 132

__device__ __forceinline__ void gemm_core_tc(
    const float* __restrict__ A, int lda,
    const float* __restrict__ B, int ldb,
    float* __restrict__ C, int ldc,
    int Kd)
{
    __shared__ uint32_t As[BM * SA];
    __shared__ uint32_t Bs[BK * SB];

    const int tid = threadIdx.x;
    const int lane = tid & 31;
    const int wid = tid >> 5;
    const int wm0 = (wid >> 1) * 32;
    const int wn0 = (wid & 1) * 64;
    const int gID = lane >> 2;
    const int tig = lane & 3;

    const int row0 = blockIdx.y * BM;
    const int col0 = blockIdx.x * BN;

    float acc[2][8][4];
    #pragma unroll
    for (int mt = 0; mt < 2; mt++)
        #pragma unroll
        for (int nt = 0; nt < 8; nt++)
            #pragma unroll
            for (int i = 0; i < 4; i++) acc[mt][nt][i] = 0.f;

    for (int k0 = 0; k0 < Kd; k0 += BK) {
        {
            const int r0 = tid >> 3;
            const int c4 = (tid & 7) * 4;
            #pragma unroll
            for (int r = 0; r < 4; r++) {
                int m = r0 + r * 32;
                float4 v = *(const float4*)(A + (long)(row0 + m) * lda + k0 + c4);
                As[m * SA + c4 + 0] = f2tf32(v.x);
                As[m * SA + c4 + 1] = f2tf32(v.y);
                As[m * SA + c4 + 2] = f2tf32(v.z);
                As[m * SA + c4 + 3] = f2tf32(v.w);
            }
        }
        {
            const int kk0 = tid >> 5;
            const int c4 = (tid & 31) * 4;
            #pragma unroll
            for (int r = 0; r < 4; r++) {
                int k = kk0 + r * 8;
                float4 v = *(const float4*)(B + (long)(k0 + k) * ldb + col0 + c4);
                uint4 u;
                u.x = f2tf32(v.x); u.y = f2tf32(v.y);
                u.z = f2tf32(v.z); u.w = f2tf32(v.w);
                *(uint4*)&Bs[k * SB + c4] = u;
            }
        }
        __syncthreads();

        #pragma unroll
        for (int kk = 0; kk < BK; kk += 8) {
            uint32_t af[2][4];
            uint32_t bf[8][2];
            #pragma unroll
            for (int mt = 0; mt < 2; mt++) {
                int r = wm0 + mt * 16 + gID;
                af[mt][0] = As[r * SA + kk + tig];
                af[mt][1] = As[(r + 8) * SA + kk + tig];
                af[mt][2] = As[r * SA + kk + tig + 4];
                af[mt][3] = As[(r + 8) * SA + kk + tig + 4];
            }
            #pragma unroll
            for (int nt = 0; nt < 8; nt++) {
                int n = wn0 + nt * 8 + gID;
                bf[nt][0] = Bs[(kk + tig) * SB + n];
                bf[nt][1] = Bs[(kk + tig + 4) * SB + n];
            }
            #pragma unroll
            for (int mt = 0; mt < 2; mt++)
                #pragma unroll
                for (int nt = 0; nt < 8; nt++)
                    mma_tf32(acc[mt][nt], af[mt], bf[nt]);
        }
        __syncthreads();
    }

    #pragma unroll
    for (int mt = 0; mt < 2; mt++) {
        int r = row0 + wm0 + mt * 16 + gID;
        #pragma unroll
        for (int nt = 0; nt < 8; nt++) {
            int c = col0 + wn0 + nt * 8 + 2 * tig;
            *(float2*)(C + (long)r * ldc + c) = make_float2(acc[mt][nt][0], acc[mt][nt][1]);
            *(float2*)(C + (long)(r + 8) * ldc + c) = make_float2(acc[mt][nt][2], acc[mt][nt][3]);
        }
    }
}

__global__ void __launch_bounds__(256) k_proj_q(const float* __restrict__ x, const float* __restrict__ W) {
    gemm_core_tc(x, Cc, W, QW, g_q, QW, Cc);
}
__global__ void __launch_bounds__(256) k_proj_k(const float* __restrict__ x, const float* __restrict__ W) {
    gemm_core_tc(x, Cc, W, KW, g_k, KW, Cc);
}
__global__ void __launch_bounds__(256) k_proj_v(const float* __restrict__ x, const float* __restrict__ W) {
    gemm_core_tc(x, Cc, W, KW, g_v, KW, Cc);
}
__global__ void __launch_bounds__(256) k_out(const float* __restrict__ Wout, float* __restrict__ out) {
    gemm_core_tc(g_enc, QW, Wout, Cc, out, Cc, QW);
}

// ---------------- Fused flash attention ----------------
// CTA: 128 q rows of one (b, head). Loop over 16 chunks of 128 keys.
// Smem (dynamic): Qs[128][132] tf32, Ks[128][132] (h-major; reused as Ps[t][s]), Vs[128][132].
#define FS 132
#define FCHUNK 128

__global__ void __launch_bounds__(256) k_flash() {
    extern __shared__ uint32_t dsm[];
    uint32_t* Qs = dsm;                    // [t][h] t-major, stride FS
    uint32_t* Ks = dsm + 128 * FS;         // [h][s]; later Ps [t][s]
    uint32_t* Vs = dsm + 2 * 128 * FS;     // [s][h]
    __shared__ float sm_m[256];            // [row][warp_n]
    __shared__ float sm_s[256];

    const int tid = threadIdx.x;
    const int lane = tid & 31;
    const int wid = tid >> 5;
    const int warp_n = wid & 1;
    const int wm0 = (wid >> 1) * 32;
    const int wn0 = warp_n * 64;
    const int gID = lane >> 2;
    const int tig = lane & 3;

    const int t0 = blockIdx.x * 128;
    const int z = blockIdx.y;             // b*16 + n
    const int b = z >> 4;
    const int n = z & 15;
    const int kh = n >> 2;

    const float* Qg = g_q + (long)b * Tt * QW + n * Hd;
    const float* Kg = g_k + (long)b * Tt * KW + kh * Hd;
    const float* Vg = g_v + (long)b * Tt * KW + kh * Hd;

    // ---- load Q tile (128 x 128) -> Qs tf32
    {
        const int r0 = tid >> 5;              // 0..7
        const int c4 = (tid & 31) * 4;        // 0..124
        #pragma unroll
        for (int rr = 0; rr < 16; rr++) {
            int t = r0 + rr * 8;
            float4 v = *(const float4*)(Qg + (long)(t0 + t) * QW + c4);
            uint4 u;
            u.x = f2tf32(v.x); u.y = f2tf32(v.y);
            u.z = f2tf32(v.z); u.w = f2tf32(v.w);
            *(uint4*)&Qs[t * FS + c4] = u;
        }
    }

    float acc_o[2][8][4];
    #pragma unroll
    for (int mt = 0; mt < 2; mt++)
        #pragma unroll
        for (int nt = 0; nt < 8; nt++)
            #pragma unroll
            for (int i = 0; i < 4; i++) acc_o[mt][nt][i] = 0.f;
    float m_run[2][2], l_run[2][2];
    #pragma unroll
    for (int mt = 0; mt < 2; mt++) {
        m_run[mt][0] = -INFINITY; m_run[mt][1] = -INFINITY;
        l_run[mt][0] = 0.f;       l_run[mt][1] = 0.f;
    }

    for (int s0 = 0; s0 < Tt; s0 += FCHUNK) {
        __syncthreads();   // prev PV reads done before Ks/Vs overwrite (also covers Q load 1st iter)

        // ---- load K chunk -> Ks[h][s]
        {
            const int sl = tid >> 2;          // 0..63
            const int c4 = (tid & 3) * 4;     // 0,4,8,12
            #pragma unroll
            for (int hh = 0; hh < 8; hh++) {
                int h = c4 + hh * 16;
                #pragma unroll
                for (int r = 0; r < 2; r++) {
                    int s = sl + r * 64;
                    float4 v = *(const float4*)(Kg + (long)(s0 + s) * KW + h);
                    Ks[(h + 0) * FS + s] = f2tf32(v.x);
                    Ks[(h + 1) * FS + s] = f2tf32(v.y);
                    Ks[(h + 2) * FS + s] = f2tf32(v.z);
                    Ks[(h + 3) * FS + s] = f2tf32(v.w);
                }
            }
        }
        // ---- load V chunk -> Vs[s][h]
        {
            const int r0 = tid >> 5;
            const int c4 = (tid & 31) * 4;
            #pragma unroll
            for (int rr = 0; rr < 16; rr++) {
                int s = r0 + rr * 8;
                float4 v = *(const float4*)(Vg + (long)(s0 + s) * KW + c4);
                uint4 u;
                u.x = f2tf32(v.x); u.y = f2tf32(v.y);
                u.z = f2tf32(v.z); u.w = f2tf32(v.w);
                *(uint4*)&Vs[s * FS + c4] = u;
            }
        }
        __syncthreads();

        // ---- S = Q K^T  (128x128x128)
        float acc_s[2][8][4];
        #pragma unroll
        for (int mt = 0; mt < 2; mt++)
            #pragma unroll
            for (int nt = 0; nt < 8; nt++)
                #pragma unroll
                for (int i = 0; i < 4; i++) acc_s[mt][nt][i] = 0.f;

        #pragma unroll
        for (int kk = 0; kk < Hd; kk += 8) {
            uint32_t af[2][4], bf[8][2];
            #pragma unroll
            for (int mt = 0; mt < 2; mt++) {
                int r = wm0 + mt * 16 + gID;
                af[mt][0] = Qs[r * FS + kk + tig];
                af[mt][1] = Qs[(r + 8) * FS + kk + tig];
                af[mt][2] = Qs[r * FS + kk + tig + 4];
                af[mt][3] = Qs[(r + 8) * FS + kk + tig + 4];
            }
            #pragma unroll
            for (int nt = 0; nt < 8; nt++) {
                int s = wn0 + nt * 8 + gID;
                bf[nt][0] = Ks[(kk + tig) * FS + s];
                bf[nt][1] = Ks[(kk + tig + 4) * FS + s];
            }
            #pragma unroll
            for (int mt = 0; mt < 2; mt++)
                #pragma unroll
                for (int nt = 0; nt < 8; nt++)
                    mma_tf32(acc_s[mt][nt], af[mt], bf[nt]);
        }

        // ---- row max (warp tig-reduce, then cross warp_n via smem)
        float mx[2][2];
        #pragma unroll
        for (int mt = 0; mt < 2; mt++) {
            float m0 = -INFINITY, m1 = -INFINITY;
            #pragma unroll
            for (int nt = 0; nt < 8; nt++) {
                m0 = fmaxf(m0, fmaxf(acc_s[mt][nt][0], acc_s[mt][nt][1]));
                m1 = fmaxf(m1, fmaxf(acc_s[mt][nt][2], acc_s[mt][nt][3]));
            }
            #pragma unroll
            for (int off = 1; off <= 2; off <<= 1) {
                m0 = fmaxf(m0, __shfl_xor_sync(0xffffffffu, m0, off));
                m1 = fmaxf(m1, __shfl_xor_sync(0xffffffffu, m1, off));
            }
            mx[mt][0] = m0; mx[mt][1] = m1;
            if (tig == 0) {
                int r = wm0 + mt * 16 + gID;
                sm_m[r * 2 + warp_n] = m0;
                sm_m[(r + 8) * 2 + warp_n] = m1;
            }
        }
        __syncthreads();

        float mnew[2][2], pscale[2][2];
        #pragma unroll
        for (int mt = 0; mt < 2; mt++) {
            int r = wm0 + mt * 16 + gID;
            float c0 = fmaxf(sm_m[r * 2], sm_m[r * 2 + 1]);
            float c1 = fmaxf(sm_m[(r + 8) * 2], sm_m[(r + 8) * 2 + 1]);
            mnew[mt][0] = fmaxf(m_run[mt][0], c0);
            mnew[mt][1] = fmaxf(m_run[mt][1], c1);
            pscale[mt][0] = __expf(m_run[mt][0] - mnew[mt][0]);
            pscale[mt][1] = __expf(m_run[mt][1] - mnew[mt][1]);
            m_run[mt][0] = mnew[mt][0];
            m_run[mt][1] = mnew[mt][1];
        }

        // ---- P = exp(S - m), rescale O, row sum
        #pragma unroll
        for (int mt = 0; mt < 2; mt++) {
            float s0sum = 0.f, s1sum = 0.f;
            #pragma unroll
            for (int nt = 0; nt < 8; nt++) {
                acc_s[mt][nt][0] = __expf(acc_s[mt][nt][0] - mnew[mt][0]);
                acc_s[mt][nt][1] = __expf(acc_s[mt][nt][1] - mnew[mt][0]);
                acc_s[mt][nt][2] = __expf(acc_s[mt][nt][2] - mnew[mt][1]);
                acc_s[mt][nt][3] = __expf(acc_s[mt][nt][3] - mnew[mt][1]);
                s0sum += acc_s[mt][nt][0] + acc_s[mt][nt][1];
                s1sum += acc_s[mt][nt][2] + acc_s[mt][nt][3];
                acc_o[mt][nt][0] *= pscale[mt][0];
                acc_o[mt][nt][1] *= pscale[mt][0];
                acc_o[mt][nt][2] *= pscale[mt][1];
                acc_o[mt][nt][3] *= pscale[mt][1];
            }
            #pragma unroll
            for (int off = 1; off <= 2; off <<= 1) {
                s0sum += __shfl_xor_sync(0xffffffffu, s0sum, off);
                s1sum += __shfl_xor_sync(0xffffffffu, s1sum, off);
            }
            if (tig == 0) {
                int r = wm0 + mt * 16 + gID;
                sm_s[r * 2 + warp_n] = s0sum;
                sm_s[(r + 8) * 2 + warp_n] = s1sum;
            }
        }

        // ---- write P into Ps (= Ks region, safe: all warps past S-mma)
        #pragma unroll
        for (int mt = 0; mt < 2; mt++) {
            int r = wm0 + mt * 16 + gID;
            #pragma unroll
            for (int nt = 0; nt < 8; nt++) {
                int c = wn0 + nt * 8 + 2 * tig;
                uint2 u0 = make_uint2(f2tf32(acc_s[mt][nt][0]), f2tf32(acc_s[mt][nt][1]));
                uint2 u1 = make_uint2(f2tf32(acc_s[mt][nt][2]), f2tf32(acc_s[mt][nt][3]));
                *(uint2*)&Ks[r * FS + c] = u0;
                *(uint2*)&Ks[(r + 8) * FS + c] = u1;
            }
        }
        __syncthreads();

        // combine row sums
        #pragma unroll
        for (int mt = 0; mt < 2; mt++) {
            int r = wm0 + mt * 16 + gID;
            float c0 = sm_s[r * 2] + sm_s[r * 2 + 1];
            float c1 = sm_s[(r + 8) * 2] + sm_s[(r + 8) * 2 + 1];
            l_run[mt][0] = l_run[mt][0] * pscale[mt][0] + c0;
            l_run[mt][1] = l_run[mt][1] * pscale[mt][1] + c1;
        }

        // ---- O += P V   (128x128x128), A = Ps (Ks region), B = Vs
        #pragma unroll
        for (int kk = 0; kk < FCHUNK; kk += 8) {
            uint32_t af[2][4], bf[8][2];
            #pragma unroll
            for (int mt = 0; mt < 2; mt++) {
                int r = wm0 + mt * 16 + gID;
                af[mt][0] = Ks[r * FS + kk + tig];
                af[mt][1] = Ks[(r + 8) * FS + kk + tig];
                af[mt][2] = Ks[r * FS + kk + tig + 4];
                af[mt][3] = Ks[(r + 8) * FS + kk + tig + 4];
            }
            #pragma unroll
            for (int nt = 0; nt < 8; nt++) {
                int h = wn0 + nt * 8 + gID;
                bf[nt][0] = Vs[(kk + tig) * FS + h];
                bf[nt][1] = Vs[(kk + tig + 4) * FS + h];
            }
            #pragma unroll
            for (int mt = 0; mt < 2; mt++)
                #pragma unroll
                for (int nt = 0; nt < 8; nt++)
                    mma_tf32(acc_o[mt][nt], af[mt], bf[nt]);
        }
    }

    // ---- normalize + store to g_enc
    float* Og = g_enc + (long)b * Tt * QW + n * Hd;
    #pragma unroll
    for (int mt = 0; mt < 2; mt++) {
        float inv0 = 1.f / l_run[mt][0];
        float inv1 = 1.f / l_run[mt][1];
        int r = t0 + wm0 + mt * 16 + gID;
        #pragma unroll
        for (int nt = 0; nt < 8; nt++) {
            int c = wn0 + nt * 8 + 2 * tig;
            *(float2*)(Og + (long)r * QW + c) =
                make_float2(acc_o[mt][nt][0] * inv0, acc_o[mt][nt][1] * inv0);
            *(float2*)(Og + (long)(r + 8) * QW + c) =
                make_float2(acc_o[mt][nt][2] * inv1, acc_o[mt][nt][3] * inv1);
        }
    }
}

// ---------------- RMSNorm + RoPE (+ 1/sqrt(H) for q) ----------------
__global__ void k_qpost() {
    __shared__ float row[QW];
    __shared__ float red[256];
    const long base = (long)blockIdx.x * QW;
    const int t = blockIdx.x & (Tt - 1);
    const int tid = threadIdx.x;

    float ss = 0.f;
    for (int i = tid; i < QW; i += 256) {
        float v = g_q[base + i];
        row[i] = v;
        ss += v * v;
    }
    red[tid] = ss;
    __syncthreads();
    for (int s = 128; s > 0; s >>= 1) {
        if (tid < s) red[tid] += red[tid + s];
        __syncthreads();
    }
    const float r = rsqrtf(red[0] * (1.f / QW) + 1e-6f) * 0.088388347648318447f;
    __syncthreads();

    for (int i = tid; i < QW; i += 256) {
        int h = i & 127;
        int hh = h & 63;
        float invfreq = powf(10000.f, -(float)hh * (1.f / 64.f));
        float ang = (float)t * invfreq;
        float sv, cv;
        sincosf(ang, &sv, &cv);
        float v = row[i];
        float p = (h < 64) ? row[i + 64] : row[i - 64];
        float o = (h < 64) ? (v * cv - p * sv) : (v * cv + p * sv);
        g_q[base + i] = o * r;
    }
}

__global__ void k_kpost() {
    __shared__ float row[KW];
    __shared__ float red[128];
    const long base = (long)blockIdx.x * KW;
    const int t = blockIdx.x & (Tt - 1);
    const int tid = threadIdx.x;

    float ss = 0.f;
    for (int i = tid; i < KW; i += 128) {
        float v = g_k[base + i];
        row[i] = v;
        ss += v * v;
    }
    red[tid] = ss;
    __syncthreads();
    for (int s = 64; s > 0; s >>= 1) {
        if (tid < s) red[tid] += red[tid + s];
        __syncthreads();
    }
    const float r = rsqrtf(red[0] * (1.f / KW) + 1e-6f);
    __syncthreads();

    for (int i = tid; i < KW; i += 128) {
        int h = i & 127;
        int hh = h & 63;
        float invfreq = powf(10000.f, -(float)hh * (1.f / 64.f));
        float ang = (float)t * invfreq;
        float sv, cv;
        sincosf(ang, &sv, &cv);
        float v = row[i];
        float p = (h < 64) ? row[i + 64] : row[i - 64];
        float o = (h < 64) ? (v * cv - p * sv) : (v * cv + p * sv);
        g_k[base + i] = o * r;
    }
}

// ---------------- launch ----------------
extern "C" void kernel_launch(void* const* d_in, const int* in_sizes, int n_in,
                              void* d_out, int out_size) {
    const float* x    = (const float*)d_in[0];
    const float* Wq   = (const float*)d_in[1];
    const float* Wk   = (const float*)d_in[2];
    const float* Wv   = (const float*)d_in[3];
    const float* Wout = (const float*)d_in[4];
    float* out = (float*)d_out;

    const int FLASH_SMEM = 3 * 128 * FS * 4;   // 202752 bytes
    cudaFuncSetAttribute(k_flash, cudaFuncAttributeMaxDynamicSharedMemorySize, FLASH_SMEM);

    // projections
    k_proj_q<<<dim3(QW / BN, BT / BM), 256>>>(x, Wq);
    k_proj_k<<<dim3(KW / BN, BT / BM), 256>>>(x, Wk);
    k_proj_v<<<dim3(KW / BN, BT / BM), 256>>>(x, Wv);

    // rmsnorm + rope (+ scale for q)
    k_qpost<<<BT, 256>>>();
    k_kpost<<<BT, 128>>>();

    // fused attention
    k_flash<<<dim3(Tt / 128, Bb * NH), 256, FLASH_SMEM>>>();

    // output projection
    k_out<<<dim3(Cc / BN, BT / BM), 256>>>(Wout, out);
}

// round 12
// speedup vs baseline: 1.0621x; 1.0621x over previous
#include <cuda_runtime.h>
#include <cuda_bf16.h>
#include <math.h>
#include <stdint.h>

// Problem dims
#define Bb 4
#define Tt 2048
#define Cc 2048
#define NH 16      // q heads
#define KH 4       // kv heads
#define Hd 128
#define BT (Bb*Tt)          // 8192
#define QW (NH*Hd)          // 2048
#define KW (KH*Hd)          // 512

// Scratch (static device arrays; allocation-free per harness rules)
__device__ float g_q[(size_t)BT*QW];
__device__ float g_k[(size_t)BT*KW];
__device__ float g_v[(size_t)BT*KW];
__device__ float g_enc[(size_t)BT*QW];

// ---------------- TF32 helpers ----------------
__device__ __forceinline__ uint32_t f2tf32(float f) {
    uint32_t r;
    asm("cvt.rna.tf32.f32 %0, %1;" : "=r"(r) : "f"(f));
    return r;
}

__device__ __forceinline__ void mma_tf32(float* c, const uint32_t* a, const uint32_t* b) {
    asm volatile(
        "mma.sync.aligned.m16n8k8.row.col.f32.tf32.tf32.f32 "
        "{%0,%1,%2,%3}, {%4,%5,%6,%7}, {%8,%9}, {%0,%1,%2,%3};\n"
        : "+f"(c[0]), "+f"(c[1]), "+f"(c[2]), "+f"(c[3])
        : "r"(a[0]), "r"(a[1]), "r"(a[2]), "r"(a[3]), "r"(b[0]), "r"(b[1]));
}

// ---------------- Pipelined TF32 GEMM core (projections / out) ----------------
// 128x128 CTA tile, BK=32, 256 thr, 8 warps (4x2), warp tile 32x64.
// 2-stage smem double buffering with register prefetch; one barrier per k-iter.
#define BM 128
#define BN 128
#define BK 32
#define SA 36
#define SB 132
#define A_WORDS (BM*SA)          // 4608
#define B_WORDS (BK*SB)          // 4224
#define GEMM_SMEM ((A_WORDS + B_WORDS) * 2 * 4)   // 70656 bytes

__device__ __forceinline__ void gemm_core_pipe(
    const float* __restrict__ A, int lda,
    const float* __restrict__ B, int ldb,
    float* __restrict__ C, int ldc,
    int Kd)
{
    extern __shared__ uint32_t dsm_g[];
    uint32_t* As = dsm_g;                    // [2][BM][SA]
    uint32_t* Bs = dsm_g + 2 * A_WORDS;      // [2][BK][SB]

    const int tid = threadIdx.x;
    const int lane = tid & 31;
    const int wid = tid >> 5;
    const int wm0 = (wid >> 1) * 32;
    const int wn0 = (wid & 1) * 64;
    const int gID = lane >> 2;
    const int tig = lane & 3;

    const int row0 = blockIdx.y * BM;
    const int col0 = blockIdx.x * BN;

    // load-slot assignment
    const int a_r0 = tid >> 3;            // 0..31
    const int a_c4 = (tid & 7) * 4;       // 0..28
    const int b_k0 = tid >> 5;            // 0..7
    const int b_c4 = (tid & 31) * 4;      // 0..124

    float acc[2][8][4];
    #pragma unroll
    for (int mt = 0; mt < 2; mt++)
        #pragma unroll
        for (int nt = 0; nt < 8; nt++)
            #pragma unroll
            for (int i = 0; i < 4; i++) acc[mt][nt][i] = 0.f;

    float4 ra[4], rb[4];

    // prologue: load tile 0
    #pragma unroll
    for (int r = 0; r < 4; r++)
        ra[r] = *(const float4*)(A + (long)(row0 + a_r0 + r * 32) * lda + a_c4);
    #pragma unroll
    for (int r = 0; r < 4; r++)
        rb[r] = *(const float4*)(B + (long)(b_k0 + r * 8) * ldb + col0 + b_c4);
    {
        #pragma unroll
        for (int r = 0; r < 4; r++) {
            int m = a_r0 + r * 32;
            As[m * SA + a_c4 + 0] = f2tf32(ra[r].x);
            As[m * SA + a_c4 + 1] = f2tf32(ra[r].y);
            As[m * SA + a_c4 + 2] = f2tf32(ra[r].z);
            As[m * SA + a_c4 + 3] = f2tf32(ra[r].w);
        }
        #pragma unroll
        for (int r = 0; r < 4; r++) {
            int k = b_k0 + r * 8;
            uint4 u;
            u.x = f2tf32(rb[r].x); u.y = f2tf32(rb[r].y);
            u.z = f2tf32(rb[r].z); u.w = f2tf32(rb[r].w);
            *(uint4*)&Bs[k * SB + b_c4] = u;
        }
    }
    __syncthreads();

    const int niter = Kd / BK;
    for (int it = 0; it < niter; it++) {
        const int stage = it & 1;
        const uint32_t* Asc = As + stage * A_WORDS;
        const uint32_t* Bsc = Bs + stage * B_WORDS;
        const bool has_next = (it + 1 < niter);

        // prefetch next tile into registers (latency overlapped with MMAs)
        if (has_next) {
            const int k0n = (it + 1) * BK;
            #pragma unroll
            for (int r = 0; r < 4; r++)
                ra[r] = *(const float4*)(A + (long)(row0 + a_r0 + r * 32) * lda + k0n + a_c4);
            #pragma unroll
            for (int r = 0; r < 4; r++)
                rb[r] = *(const float4*)(B + (long)(k0n + b_k0 + r * 8) * ldb + col0 + b_c4);
        }

        // compute current stage
        #pragma unroll
        for (int kk = 0; kk < BK; kk += 8) {
            uint32_t af[2][4], bf[8][2];
            #pragma unroll
            for (int mt = 0; mt < 2; mt++) {
                int r = wm0 + mt * 16 + gID;
                af[mt][0] = Asc[r * SA + kk + tig];
                af[mt][1] = Asc[(r + 8) * SA + kk + tig];
                af[mt][2] = Asc[r * SA + kk + tig + 4];
                af[mt][3] = Asc[(r + 8) * SA + kk + tig + 4];
            }
            #pragma unroll
            for (int nt = 0; nt < 8; nt++) {
                int n = wn0 + nt * 8 + gID;
                bf[nt][0] = Bsc[(kk + tig) * SB + n];
                bf[nt][1] = Bsc[(kk + tig + 4) * SB + n];
            }
            #pragma unroll
            for (int mt = 0; mt < 2; mt++)
                #pragma unroll
                for (int nt = 0; nt < 8; nt++)
                    mma_tf32(acc[mt][nt], af[mt], bf[nt]);
        }

        // store prefetched tile into the other stage
        if (has_next) {
            uint32_t* Asn = As + (stage ^ 1) * A_WORDS;
            uint32_t* Bsn = Bs + (stage ^ 1) * B_WORDS;
            #pragma unroll
            for (int r = 0; r < 4; r++) {
                int m = a_r0 + r * 32;
                Asn[m * SA + a_c4 + 0] = f2tf32(ra[r].x);
                Asn[m * SA + a_c4 + 1] = f2tf32(ra[r].y);
                Asn[m * SA + a_c4 + 2] = f2tf32(ra[r].z);
                Asn[m * SA + a_c4 + 3] = f2tf32(ra[r].w);
            }
            #pragma unroll
            for (int r = 0; r < 4; r++) {
                int k = b_k0 + r * 8;
                uint4 u;
                u.x = f2tf32(rb[r].x); u.y = f2tf32(rb[r].y);
                u.z = f2tf32(rb[r].z); u.w = f2tf32(rb[r].w);
                *(uint4*)&Bsn[k * SB + b_c4] = u;
            }
        }
        __syncthreads();
    }

    #pragma unroll
    for (int mt = 0; mt < 2; mt++) {
        int r = row0 + wm0 + mt * 16 + gID;
        #pragma unroll
        for (int nt = 0; nt < 8; nt++) {
            int c = col0 + wn0 + nt * 8 + 2 * tig;
            *(float2*)(C + (long)r * ldc + c) = make_float2(acc[mt][nt][0], acc[mt][nt][1]);
            *(float2*)(C + (long)(r + 8) * ldc + c) = make_float2(acc[mt][nt][2], acc[mt][nt][3]);
        }
    }
}

__global__ void __launch_bounds__(256) k_proj_q(const float* __restrict__ x, const float* __restrict__ W) {
    gemm_core_pipe(x, Cc, W, QW, g_q, QW, Cc);
}
// merged K/V projection: blockIdx.z selects weight + destination
__global__ void __launch_bounds__(256) k_proj_kv(const float* __restrict__ x,
                                                 const float* __restrict__ Wk,
                                                 const float* __restrict__ Wv) {
    const float* W = blockIdx.z ? Wv : Wk;
    float* C = blockIdx.z ? g_v : g_k;
    gemm_core_pipe(x, Cc, W, KW, C, KW, Cc);
}
__global__ void __launch_bounds__(256) k_out(const float* __restrict__ Wout, float* __restrict__ out) {
    gemm_core_pipe(g_enc, QW, Wout, Cc, out, Cc, QW);
}

// ---------------- Fused flash attention (unchanged from R3) ----------------
#define FS 132
#define FCHUNK 128

__global__ void __launch_bounds__(256) k_flash() {
    extern __shared__ uint32_t dsm[];
    uint32_t* Qs = dsm;                    // [t][h] t-major, stride FS
    uint32_t* Ks = dsm + 128 * FS;         // [h][s]; later Ps [t][s]
    uint32_t* Vs = dsm + 2 * 128 * FS;     // [s][h]
    __shared__ float sm_m[256];
    __shared__ float sm_s[256];

    const int tid = threadIdx.x;
    const int lane = tid & 31;
    const int wid = tid >> 5;
    const int warp_n = wid & 1;
    const int wm0 = (wid >> 1) * 32;
    const int wn0 = warp_n * 64;
    const int gID = lane >> 2;
    const int tig = lane & 3;

    const int t0 = blockIdx.x * 128;
    const int z = blockIdx.y;
    const int b = z >> 4;
    const int n = z & 15;
    const int kh = n >> 2;

    const float* Qg = g_q + (long)b * Tt * QW + n * Hd;
    const float* Kg = g_k + (long)b * Tt * KW + kh * Hd;
    const float* Vg = g_v + (long)b * Tt * KW + kh * Hd;

    {
        const int r0 = tid >> 5;
        const int c4 = (tid & 31) * 4;
        #pragma unroll
        for (int rr = 0; rr < 16; rr++) {
            int t = r0 + rr * 8;
            float4 v = *(const float4*)(Qg + (long)(t0 + t) * QW + c4);
            uint4 u;
            u.x = f2tf32(v.x); u.y = f2tf32(v.y);
            u.z = f2tf32(v.z); u.w = f2tf32(v.w);
            *(uint4*)&Qs[t * FS + c4] = u;
        }
    }

    float acc_o[2][8][4];
    #pragma unroll
    for (int mt = 0; mt < 2; mt++)
        #pragma unroll
        for (int nt = 0; nt < 8; nt++)
            #pragma unroll
            for (int i = 0; i < 4; i++) acc_o[mt][nt][i] = 0.f;
    float m_run[2][2], l_run[2][2];
    #pragma unroll
    for (int mt = 0; mt < 2; mt++) {
        m_run[mt][0] = -INFINITY; m_run[mt][1] = -INFINITY;
        l_run[mt][0] = 0.f;       l_run[mt][1] = 0.f;
    }

    for (int s0 = 0; s0 < Tt; s0 += FCHUNK) {
        __syncthreads();

        {
            const int sl = tid >> 2;
            const int c4 = (tid & 3) * 4;
            #pragma unroll
            for (int hh = 0; hh < 8; hh++) {
                int h = c4 + hh * 16;
                #pragma unroll
                for (int r = 0; r < 2; r++) {
                    int s = sl + r * 64;
                    float4 v = *(const float4*)(Kg + (long)(s0 + s) * KW + h);
                    Ks[(h + 0) * FS + s] = f2tf32(v.x);
                    Ks[(h + 1) * FS + s] = f2tf32(v.y);
                    Ks[(h + 2) * FS + s] = f2tf32(v.z);
                    Ks[(h + 3) * FS + s] = f2tf32(v.w);
                }
            }
        }
        {
            const int r0 = tid >> 5;
            const int c4 = (tid & 31) * 4;
            #pragma unroll
            for (int rr = 0; rr < 16; rr++) {
                int s = r0 + rr * 8;
                float4 v = *(const float4*)(Vg + (long)(s0 + s) * KW + c4);
                uint4 u;
                u.x = f2tf32(v.x); u.y = f2tf32(v.y);
                u.z = f2tf32(v.z); u.w = f2tf32(v.w);
                *(uint4*)&Vs[s * FS + c4] = u;
            }
        }
        __syncthreads();

        float acc_s[2][8][4];
        #pragma unroll
        for (int mt = 0; mt < 2; mt++)
            #pragma unroll
            for (int nt = 0; nt < 8; nt++)
                #pragma unroll
                for (int i = 0; i < 4; i++) acc_s[mt][nt][i] = 0.f;

        #pragma unroll
        for (int kk = 0; kk < Hd; kk += 8) {
            uint32_t af[2][4], bf[8][2];
            #pragma unroll
            for (int mt = 0; mt < 2; mt++) {
                int r = wm0 + mt * 16 + gID;
                af[mt][0] = Qs[r * FS + kk + tig];
                af[mt][1] = Qs[(r + 8) * FS + kk + tig];
                af[mt][2] = Qs[r * FS + kk + tig + 4];
                af[mt][3] = Qs[(r + 8) * FS + kk + tig + 4];
            }
            #pragma unroll
            for (int nt = 0; nt < 8; nt++) {
                int s = wn0 + nt * 8 + gID;
                bf[nt][0] = Ks[(kk + tig) * FS + s];
                bf[nt][1] = Ks[(kk + tig + 4) * FS + s];
            }
            #pragma unroll
            for (int mt = 0; mt < 2; mt++)
                #pragma unroll
                for (int nt = 0; nt < 8; nt++)
                    mma_tf32(acc_s[mt][nt], af[mt], bf[nt]);
        }

        #pragma unroll
        for (int mt = 0; mt < 2; mt++) {
            float m0 = -INFINITY, m1 = -INFINITY;
            #pragma unroll
            for (int nt = 0; nt < 8; nt++) {
                m0 = fmaxf(m0, fmaxf(acc_s[mt][nt][0], acc_s[mt][nt][1]));
                m1 = fmaxf(m1, fmaxf(acc_s[mt][nt][2], acc_s[mt][nt][3]));
            }
            #pragma unroll
            for (int off = 1; off <= 2; off <<= 1) {
                m0 = fmaxf(m0, __shfl_xor_sync(0xffffffffu, m0, off));
                m1 = fmaxf(m1, __shfl_xor_sync(0xffffffffu, m1, off));
            }
            if (tig == 0) {
                int r = wm0 + mt * 16 + gID;
                sm_m[r * 2 + warp_n] = m0;
                sm_m[(r + 8) * 2 + warp_n] = m1;
            }
        }
        __syncthreads();

        float mnew[2][2], pscale[2][2];
        #pragma unroll
        for (int mt = 0; mt < 2; mt++) {
            int r = wm0 + mt * 16 + gID;
            float c0 = fmaxf(sm_m[r * 2], sm_m[r * 2 + 1]);
            float c1 = fmaxf(sm_m[(r + 8) * 2], sm_m[(r + 8) * 2 + 1]);
            mnew[mt][0] = fmaxf(m_run[mt][0], c0);
            mnew[mt][1] = fmaxf(m_run[mt][1], c1);
            pscale[mt][0] = __expf(m_run[mt][0] - mnew[mt][0]);
            pscale[mt][1] = __expf(m_run[mt][1] - mnew[mt][1]);
            m_run[mt][0] = mnew[mt][0];
            m_run[mt][1] = mnew[mt][1];
        }

        #pragma unroll
        for (int mt = 0; mt < 2; mt++) {
            float s0sum = 0.f, s1sum = 0.f;
            #pragma unroll
            for (int nt = 0; nt < 8; nt++) {
                acc_s[mt][nt][0] = __expf(acc_s[mt][nt][0] - mnew[mt][0]);
                acc_s[mt][nt][1] = __expf(acc_s[mt][nt][1] - mnew[mt][0]);
                acc_s[mt][nt][2] = __expf(acc_s[mt][nt][2] - mnew[mt][1]);
                acc_s[mt][nt][3] = __expf(acc_s[mt][nt][3] - mnew[mt][1]);
                s0sum += acc_s[mt][nt][0] + acc_s[mt][nt][1];
                s1sum += acc_s[mt][nt][2] + acc_s[mt][nt][3];
                acc_o[mt][nt][0] *= pscale[mt][0];
                acc_o[mt][nt][1] *= pscale[mt][0];
                acc_o[mt][nt][2] *= pscale[mt][1];
                acc_o[mt][nt][3] *= pscale[mt][1];
            }
            #pragma unroll
            for (int off = 1; off <= 2; off <<= 1) {
                s0sum += __shfl_xor_sync(0xffffffffu, s0sum, off);
                s1sum += __shfl_xor_sync(0xffffffffu, s1sum, off);
            }
            if (tig == 0) {
                int r = wm0 + mt * 16 + gID;
                sm_s[r * 2 + warp_n] = s0sum;
                sm_s[(r + 8) * 2 + warp_n] = s1sum;
            }
        }

        #pragma unroll
        for (int mt = 0; mt < 2; mt++) {
            int r = wm0 + mt * 16 + gID;
            #pragma unroll
            for (int nt = 0; nt < 8; nt++) {
                int c = wn0 + nt * 8 + 2 * tig;
                uint2 u0 = make_uint2(f2tf32(acc_s[mt][nt][0]), f2tf32(acc_s[mt][nt][1]));
                uint2 u1 = make_uint2(f2tf32(acc_s[mt][nt][2]), f2tf32(acc_s[mt][nt][3]));
                *(uint2*)&Ks[r * FS + c] = u0;
                *(uint2*)&Ks[(r + 8) * FS + c] = u1;
            }
        }
        __syncthreads();

        #pragma unroll
        for (int mt = 0; mt < 2; mt++) {
            int r = wm0 + mt * 16 + gID;
            float c0 = sm_s[r * 2] + sm_s[r * 2 + 1];
            float c1 = sm_s[(r + 8) * 2] + sm_s[(r + 8) * 2 + 1];
            l_run[mt][0] = l_run[mt][0] * pscale[mt][0] + c0;
            l_run[mt][1] = l_run[mt][1] * pscale[mt][1] + c1;
        }

        #pragma unroll
        for (int kk = 0; kk < FCHUNK; kk += 8) {
            uint32_t af[2][4], bf[8][2];
            #pragma unroll
            for (int mt = 0; mt < 2; mt++) {
                int r = wm0 + mt * 16 + gID;
                af[mt][0] = Ks[r * FS + kk + tig];
                af[mt][1] = Ks[(r + 8) * FS + kk + tig];
                af[mt][2] = Ks[r * FS + kk + tig + 4];
                af[mt][3] = Ks[(r + 8) * FS + kk + tig + 4];
            }
            #pragma unroll
            for (int nt = 0; nt < 8; nt++) {
                int h = wn0 + nt * 8 + gID;
                bf[nt][0] = Vs[(kk + tig) * FS + h];
                bf[nt][1] = Vs[(kk + tig + 4) * FS + h];
            }
            #pragma unroll
            for (int mt = 0; mt < 2; mt++)
                #pragma unroll
                for (int nt = 0; nt < 8; nt++)
                    mma_tf32(acc_o[mt][nt], af[mt], bf[nt]);
        }
    }

    float* Og = g_enc + (long)b * Tt * QW + n * Hd;
    #pragma unroll
    for (int mt = 0; mt < 2; mt++) {
        float inv0 = 1.f / l_run[mt][0];
        float inv1 = 1.f / l_run[mt][1];
        int r = t0 + wm0 + mt * 16 + gID;
        #pragma unroll
        for (int nt = 0; nt < 8; nt++) {
            int c = wn0 + nt * 8 + 2 * tig;
            *(float2*)(Og + (long)r * QW + c) =
                make_float2(acc_o[mt][nt][0] * inv0, acc_o[mt][nt][1] * inv0);
            *(float2*)(Og + (long)(r + 8) * QW + c) =
                make_float2(acc_o[mt][nt][2] * inv1, acc_o[mt][nt][3] * inv1);
        }
    }
}

// ---------------- RMSNorm + RoPE (sincos table in smem) ----------------
__global__ void k_qpost() {
    __shared__ float row[QW];
    __shared__ float red[256];
    __shared__ float s_sin[64], s_cos[64];
    const long base = (long)blockIdx.x * QW;
    const int t = blockIdx.x & (Tt - 1);
    const int tid = threadIdx.x;

    if (tid < 64) {
        float invfreq = powf(10000.f, -(float)tid * (1.f / 64.f));
        sincosf((float)t * invfreq, &s_sin[tid], &s_cos[tid]);
    }

    float ss = 0.f;
    for (int i = tid; i < QW; i += 256) {
        float v = g_q[base + i];
        row[i] = v;
        ss += v * v;
    }
    red[tid] = ss;
    __syncthreads();
    for (int s = 128; s > 0; s >>= 1) {
        if (tid < s) red[tid] += red[tid + s];
        __syncthreads();
    }
    const float r = rsqrtf(red[0] * (1.f / QW) + 1e-6f) * 0.088388347648318447f;
    __syncthreads();

    for (int i = tid; i < QW; i += 256) {
        int h = i & 127;
        int hh = h & 63;
        float sv = s_sin[hh], cv = s_cos[hh];
        float v = row[i];
        float p = (h < 64) ? row[i + 64] : row[i - 64];
        float o = (h < 64) ? (v * cv - p * sv) : (v * cv + p * sv);
        g_q[base + i] = o * r;
    }
}

__global__ void k_kpost() {
    __shared__ float row[KW];
    __shared__ float red[128];
    __shared__ float s_sin[64], s_cos[64];
    const long base = (long)blockIdx.x * KW;
    const int t = blockIdx.x & (Tt - 1);
    const int tid = threadIdx.x;

    if (tid < 64) {
        float invfreq = powf(10000.f, -(float)tid * (1.f / 64.f));
        sincosf((float)t * invfreq, &s_sin[tid], &s_cos[tid]);
    }

    float ss = 0.f;
    for (int i = tid; i < KW; i += 128) {
        float v = g_k[base + i];
        row[i] = v;
        ss += v * v;
    }
    red[tid] = ss;
    __syncthreads();
    for (int s = 64; s > 0; s >>= 1) {
        if (tid < s) red[tid] += red[tid + s];
        __syncthreads();
    }
    const float r = rsqrtf(red[0] * (1.f / KW) + 1e-6f);
    __syncthreads();

    for (int i = tid; i < KW; i += 128) {
        int h = i & 127;
        int hh = h & 63;
        float sv = s_sin[hh], cv = s_cos[hh];
        float v = row[i];
        float p = (h < 64) ? row[i + 64] : row[i - 64];
        float o = (h < 64) ? (v * cv - p * sv) : (v * cv + p * sv);
        g_k[base + i] = o * r;
    }
}

// ---------------- launch ----------------
extern "C" void kernel_launch(void* const* d_in, const int* in_sizes, int n_in,
                              void* d_out, int out_size) {
    const float* x    = (const float*)d_in[0];
    const float* Wq   = (const float*)d_in[1];
    const float* Wk   = (const float*)d_in[2];
    const float* Wv   = (const float*)d_in[3];
    const float* Wout = (const float*)d_in[4];
    float* out = (float*)d_out;

    const int FLASH_SMEM = 3 * 128 * FS * 4;   // 202752 bytes
    cudaFuncSetAttribute(k_flash, cudaFuncAttributeMaxDynamicSharedMemorySize, FLASH_SMEM);
    cudaFuncSetAttribute(k_proj_q,  cudaFuncAttributeMaxDynamicSharedMemorySize, GEMM_SMEM);
    cudaFuncSetAttribute(k_proj_kv, cudaFuncAttributeMaxDynamicSharedMemorySize, GEMM_SMEM);
    cudaFuncSetAttribute(k_out,     cudaFuncAttributeMaxDynamicSharedMemorySize, GEMM_SMEM);

    // projections
    k_proj_q<<<dim3(QW / BN, BT / BM), 256, GEMM_SMEM>>>(x, Wq);
    k_proj_kv<<<dim3(KW / BN, BT / BM, 2), 256, GEMM_SMEM>>>(x, Wk, Wv);

    // rmsnorm + rope (+ scale for q)
    k_qpost<<<BT, 256>>>();
    k_kpost<<<BT, 128>>>();

    // fused attention
    k_flash<<<dim3(Tt / 128, Bb * NH), 256, FLASH_SMEM>>>();

    // output projection
    k_out<<<dim3(Cc / BN, BT / BM), 256, GEMM_SMEM>>>(Wout, out);
}